// round 2
// baseline (speedup 1.0000x reference)
#include <cuda_runtime.h>
#include <cuda_bf16.h>

#define TT 4
#define NN 50000
#define DH 64
#define EE 800000
#define ROWS (TT*NN)       // 200000
#define NBANK 64
#define BN_EPS 1e-5f

// ---------------- device scratch (static, no allocs) ----------------
__device__ __align__(16) float d_avg[(size_t)ROWS*DH];   // 51.2 MB avg_neighbor
__device__ int   d_cnt[NN];
__device__ int   d_offs[NN+1];
__device__ int   d_cursor[NN];
__device__ float d_Z[NN];
__device__ int   d_csr_src[EE];
__device__ float d_csr_w[EE];
// banks: [bank][stat][col], stats: 0 sumAll,1 sqAll,2 sumLast,3 sqLast,4 sumAvg,5 sqAvg
__device__ float d_banks[NBANK*6*64];
__device__ __align__(16) float d_Wt2[192*64];  // [j][k]: W1[k,j]*scale_j
__device__ __align__(16) float d_bp[64];

// ---------------- kernels ----------------
__global__ void k_zero() {
    int i = blockIdx.x*256 + threadIdx.x;
    if (i < NN) { d_cnt[i] = 0; d_Z[i] = 0.f; }
    if (i < NBANK*6*64) d_banks[i] = 0.f;
}

__global__ void k_hist(const float* __restrict__ ew, const int* __restrict__ dst) {
    int e = blockIdx.x*256 + threadIdx.x;
    if (e < EE) {
        int d = dst[e];
        atomicAdd(&d_cnt[d], 1);
        atomicAdd(&d_Z[d], ew[e]);
    }
}

// single-block exclusive scan over d_cnt (warp-shfl based)
__global__ void k_scan() {
    __shared__ int wsum[32];
    __shared__ int wpre[32];
    __shared__ int tot_sh;
    __shared__ int carry_sh;
    int tid = threadIdx.x, lane = tid & 31, wid = tid >> 5;
    if (tid == 0) carry_sh = 0;
    __syncthreads();
    for (int base = 0; base < NN; base += 1024) {
        int i = base + tid;
        int v = (i < NN) ? d_cnt[i] : 0;
        int incl = v;
        #pragma unroll
        for (int s = 1; s < 32; s <<= 1) {
            int t = __shfl_up_sync(0xffffffffu, incl, s);
            if (lane >= s) incl += t;
        }
        if (lane == 31) wsum[wid] = incl;
        __syncthreads();
        if (wid == 0) {
            int x = wsum[lane];
            int xi = x;
            #pragma unroll
            for (int s = 1; s < 32; s <<= 1) {
                int t = __shfl_up_sync(0xffffffffu, xi, s);
                if (lane >= s) xi += t;
            }
            wpre[lane] = xi - x;
            if (lane == 31) tot_sh = xi;
        }
        __syncthreads();
        int excl = incl - v + wpre[wid] + carry_sh;
        if (i < NN) { d_offs[i] = excl; d_cursor[i] = excl; }
        __syncthreads();
        if (tid == 0) carry_sh += tot_sh;
        __syncthreads();
    }
    if (tid == 0) d_offs[NN] = carry_sh;
}

__global__ void k_fill(const float* __restrict__ ew, const int* __restrict__ src,
                       const int* __restrict__ dst) {
    int e = blockIdx.x*256 + threadIdx.x;
    if (e < EE) {
        int d = dst[e];
        int p = atomicAdd(&d_cursor[d], 1);
        d_csr_src[p] = src[e];
        d_csr_w[p]   = ew[e];
    }
}

// per-column stats of node_data (all t, and last t separately)
__global__ void __launch_bounds__(256) k_nodestats(const float* __restrict__ x) {
    float sA = 0.f, qA = 0.f, sL = 0.f, qL = 0.f;
    int tid = blockIdx.x*256 + threadIdx.x;
    const int stride = 1024*256;                 // divisible by 64
    const int col = tid & 63;
    const int lastBase = 3*NN*64;
    for (int i = tid; i < ROWS*64; i += stride) {
        float v = x[i];
        sA += v; qA += v*v;
        if (i >= lastBase) { sL += v; qL += v*v; }
    }
    __shared__ float sh[4][64];
    ((float*)sh)[threadIdx.x] = 0.f;
    __syncthreads();
    atomicAdd(&sh[0][col], sA);
    atomicAdd(&sh[1][col], qA);
    atomicAdd(&sh[2][col], sL);
    atomicAdd(&sh[3][col], qL);
    __syncthreads();
    if (threadIdx.x < 64) {
        float* b = d_banks + (blockIdx.x & (NBANK-1))*(6*64);
        atomicAdd(&b[0*64 + threadIdx.x], sh[0][threadIdx.x]);
        atomicAdd(&b[1*64 + threadIdx.x], sh[1][threadIdx.x]);
        atomicAdd(&b[2*64 + threadIdx.x], sh[2][threadIdx.x]);
        atomicAdd(&b[3*64 + threadIdx.x], sh[3][threadIdx.x]);
    }
}

// gather aggregation: warp per (t,node), writes avg_neighbor + accumulates its stats
__global__ void __launch_bounds__(256) k_agg(const float* __restrict__ x) {
    int gw   = blockIdx.x*8 + (threadIdx.x >> 5);
    int lane = threadIdx.x & 31;
    __shared__ float sv[64];
    __shared__ float sq[64];
    if (threadIdx.x < 64) { sv[threadIdx.x] = 0.f; sq[threadIdx.x] = 0.f; }
    __syncthreads();
    if (gw < ROWS) {
        int t = gw / NN;
        int n = gw - t*NN;
        int e0 = d_offs[n], e1 = d_offs[n+1];
        const float* xt = x + (size_t)t*NN*64;
        float a0 = 0.f, a1 = 0.f;
        for (int base = e0; base < e1; base += 32) {
            int m = e1 - base; if (m > 32) m = 32;
            int   s = 0; float w = 0.f;
            if (lane < m) { s = d_csr_src[base+lane]; w = d_csr_w[base+lane]; }
            for (int k = 0; k < m; k++) {
                int   sk = __shfl_sync(0xffffffffu, s, k);
                float wk = __shfl_sync(0xffffffffu, w, k);
                a0 += wk * xt[sk*64 + lane];
                a1 += wk * xt[sk*64 + 32 + lane];
            }
        }
        float z = d_Z[n];
        float inv = (z == 0.f) ? 1.f : 1.f/z;     // matches reference Z[Z==0]=1
        a0 *= inv; a1 *= inv;
        d_avg[(size_t)gw*64 + lane]      = a0;
        d_avg[(size_t)gw*64 + 32 + lane] = a1;
        atomicAdd(&sv[lane],      a0); atomicAdd(&sq[lane],      a0*a0);
        atomicAdd(&sv[lane+32],   a1); atomicAdd(&sq[lane+32],   a1*a1);
    }
    __syncthreads();
    if (threadIdx.x < 64) {
        float* b = d_banks + (blockIdx.x & (NBANK-1))*(6*64);
        atomicAdd(&b[4*64 + threadIdx.x], sv[threadIdx.x]);
        atomicAdd(&b[5*64 + threadIdx.x], sq[threadIdx.x]);
    }
}

// fold BN into the GEMM: build W' (scaled, transposed) and b'
__global__ void k_finalize(const float* __restrict__ W1, const float* __restrict__ b1,
                           const float* __restrict__ gamma, const float* __restrict__ beta) {
    __shared__ float stat[6*64];
    __shared__ float s[192];
    __shared__ float tt[192];
    int tid = threadIdx.x;
    for (int k = tid; k < 6*64; k += 256) {
        float acc = 0.f;
        for (int b = 0; b < NBANK; b++) acc += d_banks[b*(6*64) + k];
        stat[k] = acc;
    }
    __syncthreads();
    if (tid < 192) {
        float sum, sq;
        if (tid < 64)       { sum = stat[0*64+tid];            sq = stat[1*64+tid]; }
        else if (tid < 128) { int c = tid-64;
                              sum = stat[0*64+c]-stat[2*64+c]; sq = stat[1*64+c]-stat[3*64+c]; }
        else                { int c = tid-128;
                              sum = stat[4*64+c];              sq = stat[5*64+c]; }
        float mu  = sum / (float)ROWS;
        float var = sq  / (float)ROWS - mu*mu;
        float sj  = gamma[tid] * rsqrtf(var + BN_EPS);
        s[tid]  = sj;
        tt[tid] = beta[tid] - mu*sj;
    }
    __syncthreads();
    for (int i = tid; i < 192*64; i += 256) {
        int j = i >> 6;          // feature
        int k = i & 63;          // output col
        d_Wt2[i] = W1[k*192 + j] * s[j];   // layout [j][k]
    }
    if (tid < 64) {
        float acc = b1[tid];
        for (int j = 0; j < 192; j++) acc += tt[j] * W1[tid*192 + j];
        d_bp[tid] = acc;
    }
}

// fused normalized GEMM + ReLU: out[row,k] = relu(sum_j inp_j * W'[j,k] + b'_k)
// 64 rows per block; 8 warps x 8 rows; lane owns 2 output cols.
__global__ void __launch_bounds__(256) k_gemm(const float* __restrict__ x,
                                              float* __restrict__ out) {
    __shared__ float rowbuf[64][64];
    __shared__ float wbuf[64][64];
    int lane = threadIdx.x & 31, warp = threadIdx.x >> 5;
    int r0 = blockIdx.x * 64;
    float acc0[8], acc1[8];
    #pragma unroll
    for (int r = 0; r < 8; r++) { acc0[r] = 0.f; acc1[r] = 0.f; }

    for (int c = 0; c < 3; c++) {
        __syncthreads();
        // stage 64 rows x 64 cols of chunk c
        for (int i = threadIdx.x; i < 1024; i += 256) {
            int row = i >> 4, cc = i & 15;
            int r = r0 + row;
            float4 v;
            if (c == 0) {
                v = ((const float4*)x)[(size_t)r*16 + cc];
            } else if (c == 1) {
                if (r < NN) v = make_float4(0.f,0.f,0.f,0.f);   // t==0 -> prev zeros
                else        v = ((const float4*)x)[(size_t)(r-NN)*16 + cc];
            } else {
                v = ((const float4*)d_avg)[(size_t)r*16 + cc];
            }
            *(float4*)&rowbuf[row][cc<<2] = v;
        }
        // stage weights chunk
        for (int i = threadIdx.x; i < 1024; i += 256)
            ((float4*)wbuf)[i] = ((const float4*)d_Wt2)[c*1024 + i];
        __syncthreads();

        #pragma unroll 4
        for (int j = 0; j < 64; j += 4) {
            float4 rv[8];
            #pragma unroll
            for (int r = 0; r < 8; r++)
                rv[r] = *(float4*)&rowbuf[warp*8 + r][j];
            #pragma unroll
            for (int jj = 0; jj < 4; jj++) {
                float2 w = *(float2*)&wbuf[j+jj][lane<<1];
                #pragma unroll
                for (int r = 0; r < 8; r++) {
                    float v = (jj==0) ? rv[r].x : (jj==1) ? rv[r].y : (jj==2) ? rv[r].z : rv[r].w;
                    acc0[r] = fmaf(v, w.x, acc0[r]);
                    acc1[r] = fmaf(v, w.y, acc1[r]);
                }
            }
        }
    }

    float2 bb = *(const float2*)&d_bp[lane<<1];
    #pragma unroll
    for (int r = 0; r < 8; r++) {
        int row = r0 + warp*8 + r;
        float2 o;
        o.x = fmaxf(acc0[r] + bb.x, 0.f);
        o.y = fmaxf(acc1[r] + bb.y, 0.f);
        ((float2*)out)[(size_t)row*32 + lane] = o;
    }
}

// ---------------- launch ----------------
extern "C" void kernel_launch(void* const* d_in, const int* in_sizes, int n_in,
                              void* d_out, int out_size) {
    const float* node  = (const float*)d_in[0];
    const float* ew    = (const float*)d_in[1];
    const float* W1    = (const float*)d_in[2];
    const float* b1    = (const float*)d_in[3];
    const float* gamma = (const float*)d_in[4];
    const float* beta  = (const float*)d_in[5];
    const int*   src   = (const int*)d_in[6];
    const int*   dst   = (const int*)d_in[7];
    float* out = (float*)d_out;

    k_zero<<<196, 256>>>();
    k_hist<<<(EE+255)/256, 256>>>(ew, dst);
    k_scan<<<1, 1024>>>();
    k_fill<<<(EE+255)/256, 256>>>(ew, src, dst);
    k_nodestats<<<1024, 256>>>(node);
    k_agg<<<(ROWS+7)/8, 256>>>(node);
    k_finalize<<<1, 256>>>(W1, b1, gamma, beta);
    k_gemm<<<ROWS/64, 256>>>(node, out);
}

// round 3
// speedup vs baseline: 1.2809x; 1.2809x over previous
#include <cuda_runtime.h>
#include <cuda_bf16.h>
#include <cstdint>

#define TT 4
#define NN 50000
#define DH 64
#define EE 800000
#define ROWS (TT*NN)       // 200000
#define NBANK 64
#define BN_EPS 1e-5f

// ---------------- device scratch (static, no allocs) ----------------
__device__ __align__(16) float d_avg[(size_t)ROWS*DH];   // 51.2 MB avg_neighbor
__device__ int   d_cnt[NN];
__device__ int   d_offs[NN+1];
__device__ int   d_cursor[NN];
__device__ float d_Z[NN];
__device__ int   d_csr_src[EE];
__device__ float d_csr_w[EE];
// banks: [bank][stat][col], stats: 0 sumAll,1 sqAll,2 sumLast,3 sqLast,4 sumAvg,5 sqAvg
__device__ float d_banks[NBANK*6*64];
// W' packed directly in m16n8k8 tf32 B-fragment order:
// idx = ((c*8+ks)*4 + ntp)*32 + lane ; .x=b0(nt=2ntp) .y=b1(2ntp) .z=b0(2ntp+1) .w=b1(2ntp+1)
__device__ __align__(16) uint4 d_Wfrag[3072];
__device__ __align__(16) float d_bp[64];

// ---------------- kernels ----------------
__global__ void k_zero() {
    int i = blockIdx.x*256 + threadIdx.x;
    if (i < NN) { d_cnt[i] = 0; d_Z[i] = 0.f; }
    if (i < NBANK*6*64) d_banks[i] = 0.f;
}

__global__ void k_hist(const float* __restrict__ ew, const int* __restrict__ dst) {
    int e = blockIdx.x*256 + threadIdx.x;
    if (e < EE) {
        int d = dst[e];
        atomicAdd(&d_cnt[d], 1);
        atomicAdd(&d_Z[d], ew[e]);
    }
}

// single-block exclusive scan over d_cnt (warp-shfl based)
__global__ void k_scan() {
    __shared__ int wsum[32];
    __shared__ int wpre[32];
    __shared__ int tot_sh;
    __shared__ int carry_sh;
    int tid = threadIdx.x, lane = tid & 31, wid = tid >> 5;
    if (tid == 0) carry_sh = 0;
    __syncthreads();
    for (int base = 0; base < NN; base += 1024) {
        int i = base + tid;
        int v = (i < NN) ? d_cnt[i] : 0;
        int incl = v;
        #pragma unroll
        for (int s = 1; s < 32; s <<= 1) {
            int t = __shfl_up_sync(0xffffffffu, incl, s);
            if (lane >= s) incl += t;
        }
        if (lane == 31) wsum[wid] = incl;
        __syncthreads();
        if (wid == 0) {
            int x = wsum[lane];
            int xi = x;
            #pragma unroll
            for (int s = 1; s < 32; s <<= 1) {
                int t = __shfl_up_sync(0xffffffffu, xi, s);
                if (lane >= s) xi += t;
            }
            wpre[lane] = xi - x;
            if (lane == 31) tot_sh = xi;
        }
        __syncthreads();
        int excl = incl - v + wpre[wid] + carry_sh;
        if (i < NN) { d_offs[i] = excl; d_cursor[i] = excl; }
        __syncthreads();
        if (tid == 0) carry_sh += tot_sh;
        __syncthreads();
    }
    if (tid == 0) d_offs[NN] = carry_sh;
}

__global__ void k_fill(const float* __restrict__ ew, const int* __restrict__ src,
                       const int* __restrict__ dst) {
    int e = blockIdx.x*256 + threadIdx.x;
    if (e < EE) {
        int d = dst[e];
        int p = atomicAdd(&d_cursor[d], 1);
        d_csr_src[p] = src[e];
        d_csr_w[p]   = ew[e];
    }
}

// per-column stats of node_data (all t, and last t separately)
__global__ void __launch_bounds__(256) k_nodestats(const float* __restrict__ x) {
    float sA = 0.f, qA = 0.f, sL = 0.f, qL = 0.f;
    int tid = blockIdx.x*256 + threadIdx.x;
    const int stride = 1024*256;                 // divisible by 64
    const int col = tid & 63;
    const int lastBase = 3*NN*64;
    for (int i = tid; i < ROWS*64; i += stride) {
        float v = x[i];
        sA += v; qA += v*v;
        if (i >= lastBase) { sL += v; qL += v*v; }
    }
    __shared__ float sh[4][64];
    ((float*)sh)[threadIdx.x] = 0.f;
    __syncthreads();
    atomicAdd(&sh[0][col], sA);
    atomicAdd(&sh[1][col], qA);
    atomicAdd(&sh[2][col], sL);
    atomicAdd(&sh[3][col], qL);
    __syncthreads();
    if (threadIdx.x < 64) {
        float* b = d_banks + (blockIdx.x & (NBANK-1))*(6*64);
        atomicAdd(&b[0*64 + threadIdx.x], sh[0][threadIdx.x]);
        atomicAdd(&b[1*64 + threadIdx.x], sh[1][threadIdx.x]);
        atomicAdd(&b[2*64 + threadIdx.x], sh[2][threadIdx.x]);
        atomicAdd(&b[3*64 + threadIdx.x], sh[3][threadIdx.x]);
    }
}

// gather aggregation: warp per node, ALL 4 timesteps fused.
// lane owns cols {2*lane, 2*lane+1} (float2). Writes avg_neighbor + its stats.
__global__ void __launch_bounds__(256) k_agg(const float* __restrict__ x) {
    int n    = blockIdx.x*8 + (threadIdx.x >> 5);
    int lane = threadIdx.x & 31;
    __shared__ float sv[64];
    __shared__ float sq[64];
    if (threadIdx.x < 64) { sv[threadIdx.x] = 0.f; sq[threadIdx.x] = 0.f; }
    __syncthreads();
    if (n < NN) {
        int e0 = d_offs[n], e1 = d_offs[n+1];
        const float2* x2 = (const float2*)x;
        float2 a0 = make_float2(0.f,0.f), a1 = a0, a2 = a0, a3 = a0;
        for (int base = e0; base < e1; base += 32) {
            int m = e1 - base; if (m > 32) m = 32;
            int   s = 0; float w = 0.f;
            if (lane < m) { s = d_csr_src[base+lane]; w = d_csr_w[base+lane]; }
            for (int k = 0; k < m; k++) {
                int    sk = __shfl_sync(0xffffffffu, s, k);
                float  wk = __shfl_sync(0xffffffffu, w, k);
                size_t ad = (size_t)sk*32 + lane;
                float2 v0 = x2[ad];
                float2 v1 = x2[(size_t)NN*32 + ad];
                float2 v2 = x2[(size_t)2*NN*32 + ad];
                float2 v3 = x2[(size_t)3*NN*32 + ad];
                a0.x = fmaf(wk, v0.x, a0.x); a0.y = fmaf(wk, v0.y, a0.y);
                a1.x = fmaf(wk, v1.x, a1.x); a1.y = fmaf(wk, v1.y, a1.y);
                a2.x = fmaf(wk, v2.x, a2.x); a2.y = fmaf(wk, v2.y, a2.y);
                a3.x = fmaf(wk, v3.x, a3.x); a3.y = fmaf(wk, v3.y, a3.y);
            }
        }
        float z = d_Z[n];
        float inv = (z == 0.f) ? 1.f : 1.f/z;     // matches reference Z[Z==0]=1
        a0.x *= inv; a0.y *= inv; a1.x *= inv; a1.y *= inv;
        a2.x *= inv; a2.y *= inv; a3.x *= inv; a3.y *= inv;
        float2* av = (float2*)d_avg;
        av[(size_t)n*32 + lane]             = a0;
        av[(size_t)(NN + n)*32 + lane]      = a1;
        av[(size_t)(2*NN + n)*32 + lane]    = a2;
        av[(size_t)(3*NN + n)*32 + lane]    = a3;
        float s0 = a0.x + a1.x + a2.x + a3.x;
        float s1 = a0.y + a1.y + a2.y + a3.y;
        float q0 = a0.x*a0.x + a1.x*a1.x + a2.x*a2.x + a3.x*a3.x;
        float q1 = a0.y*a0.y + a1.y*a1.y + a2.y*a2.y + a3.y*a3.y;
        atomicAdd(&sv[2*lane],   s0); atomicAdd(&sq[2*lane],   q0);
        atomicAdd(&sv[2*lane+1], s1); atomicAdd(&sq[2*lane+1], q1);
    }
    __syncthreads();
    if (threadIdx.x < 64) {
        float* b = d_banks + (blockIdx.x & (NBANK-1))*(6*64);
        atomicAdd(&b[4*64 + threadIdx.x], sv[threadIdx.x]);
        atomicAdd(&b[5*64 + threadIdx.x], sq[threadIdx.x]);
    }
}

__device__ __forceinline__ unsigned to_tf32(float v) {
    unsigned u;
    asm("cvt.rna.tf32.f32 %0, %1;" : "=r"(u) : "f"(v));
    return u;
}

// fold BN into GEMM: build tf32 fragment-packed W' and fp32 b'
__global__ void k_finalize(const float* __restrict__ W1, const float* __restrict__ b1,
                           const float* __restrict__ gamma, const float* __restrict__ beta) {
    __shared__ float stat[6*64];
    __shared__ float s[192];
    __shared__ float tt[192];
    int tid = threadIdx.x;
    for (int k = tid; k < 6*64; k += 256) {
        float acc = 0.f;
        for (int b = 0; b < NBANK; b++) acc += d_banks[b*(6*64) + k];
        stat[k] = acc;
    }
    __syncthreads();
    if (tid < 192) {
        float sum, sq;
        if (tid < 64)       { sum = stat[0*64+tid];            sq = stat[1*64+tid]; }
        else if (tid < 128) { int c = tid-64;
                              sum = stat[0*64+c]-stat[2*64+c]; sq = stat[1*64+c]-stat[3*64+c]; }
        else                { int c = tid-128;
                              sum = stat[4*64+c];              sq = stat[5*64+c]; }
        float mu  = sum / (float)ROWS;
        float var = sq  / (float)ROWS - mu*mu;
        float sj  = gamma[tid] * rsqrtf(var + BN_EPS);
        s[tid]  = sj;
        tt[tid] = beta[tid] - mu*sj;
    }
    __syncthreads();
    // pack W'[j][n] = W1[n*192+j]*s[j] into mma B-fragment order (tf32)
    for (int i = tid; i < 3072; i += 256) {
        int lane = i & 31;
        int ntp  = (i >> 5) & 3;
        int ksc  = i >> 7;               // c*8 + ks
        int j0   = ksc*8 + (lane & 3);   // global feature index of b0
        int n0   = ntp*16 + (lane >> 2); // output col of .x/.y
        uint4 v;
        v.x = to_tf32(W1[n0*192 + j0]       * s[j0]);
        v.y = to_tf32(W1[n0*192 + j0 + 4]   * s[j0+4]);
        v.z = to_tf32(W1[(n0+8)*192 + j0]   * s[j0]);
        v.w = to_tf32(W1[(n0+8)*192 + j0+4] * s[j0+4]);
        d_Wfrag[i] = v;
    }
    if (tid < 64) {
        float acc = b1[tid];
        for (int j = 0; j < 192; j++) acc += tt[j] * W1[tid*192 + j];
        d_bp[tid] = acc;
    }
}

__device__ __forceinline__ void mma8(float (&c)[4], const unsigned* a, unsigned b0, unsigned b1) {
    asm volatile("mma.sync.aligned.m16n8k8.row.col.f32.tf32.tf32.f32 "
        "{%0,%1,%2,%3}, {%4,%5,%6,%7}, {%8,%9}, {%0,%1,%2,%3};"
        : "+f"(c[0]), "+f"(c[1]), "+f"(c[2]), "+f"(c[3])
        : "r"(a[0]), "r"(a[1]), "r"(a[2]), "r"(a[3]), "r"(b0), "r"(b1));
}

// tensor-core GEMM+ReLU. Block = 8 warps, each warp 32 rows x 64 cols.
// A frags straight from gmem (L1-resident per-warp working set), B from smem frags.
__global__ void __launch_bounds__(256) k_gemm(const float* __restrict__ x,
                                              float* __restrict__ out) {
    __shared__ uint4 wfrag[3072];   // 48KB, all 3 chunks of W'
    for (int i = threadIdx.x; i < 3072; i += 256) wfrag[i] = d_Wfrag[i];
    __syncthreads();

    int lane = threadIdx.x & 31, warp = threadIdx.x >> 5;
    int gid = lane >> 2, tig = lane & 3;
    int rbase = blockIdx.x*256 + warp*32 + gid;  // row of a0/mt0

    float acc[2][8][4];
    #pragma unroll
    for (int mt = 0; mt < 2; mt++)
        #pragma unroll
        for (int nt = 0; nt < 8; nt++)
            #pragma unroll
            for (int q = 0; q < 4; q++) acc[mt][nt][q] = 0.f;

    int rows[4];
    #pragma unroll
    for (int i = 0; i < 4; i++) rows[i] = rbase + i*8;

    #pragma unroll
    for (int c = 0; c < 3; c++) {
        const float* base = (c == 2) ? d_avg : x;
        int shift = (c == 1) ? NN : 0;
        const float* rp[4];
        bool vld[4];
        #pragma unroll
        for (int i = 0; i < 4; i++) {
            int re = rows[i] - shift;
            vld[i] = (re >= 0) && (rows[i] < ROWS);
            rp[i]  = base + (size_t)(vld[i] ? re : 0)*64;
        }
        #pragma unroll
        for (int ks = 0; ks < 8; ks++) {
            int col = ks*8 + tig;
            unsigned a[2][4];
            #pragma unroll
            for (int mt = 0; mt < 2; mt++) {
                a[mt][0] = to_tf32(vld[2*mt]   ? rp[2*mt][col]     : 0.f);
                a[mt][1] = to_tf32(vld[2*mt+1] ? rp[2*mt+1][col]   : 0.f);
                a[mt][2] = to_tf32(vld[2*mt]   ? rp[2*mt][col+4]   : 0.f);
                a[mt][3] = to_tf32(vld[2*mt+1] ? rp[2*mt+1][col+4] : 0.f);
            }
            const uint4* wb = &wfrag[((c*8 + ks)*4)*32 + lane];
            #pragma unroll
            for (int ntp = 0; ntp < 4; ntp++) {
                uint4 b = wb[ntp*32];
                mma8(acc[0][2*ntp],   a[0], b.x, b.y);
                mma8(acc[1][2*ntp],   a[1], b.x, b.y);
                mma8(acc[0][2*ntp+1], a[0], b.z, b.w);
                mma8(acc[1][2*ntp+1], a[1], b.z, b.w);
            }
        }
    }

    float2* out2 = (float2*)out;
    const float2* bp2 = (const float2*)d_bp;
    #pragma unroll
    for (int mt = 0; mt < 2; mt++) {
        int r0 = rbase + mt*16;
        int r1 = r0 + 8;
        #pragma unroll
        for (int nt = 0; nt < 8; nt++) {
            float2 bb = bp2[nt*4 + tig];
            if (r0 < ROWS) {
                float2 o;
                o.x = fmaxf(acc[mt][nt][0] + bb.x, 0.f);
                o.y = fmaxf(acc[mt][nt][1] + bb.y, 0.f);
                out2[(size_t)r0*32 + nt*4 + tig] = o;
            }
            if (r1 < ROWS) {
                float2 o;
                o.x = fmaxf(acc[mt][nt][2] + bb.x, 0.f);
                o.y = fmaxf(acc[mt][nt][3] + bb.y, 0.f);
                out2[(size_t)r1*32 + nt*4 + tig] = o;
            }
        }
    }
}

// ---------------- launch ----------------
extern "C" void kernel_launch(void* const* d_in, const int* in_sizes, int n_in,
                              void* d_out, int out_size) {
    const float* node  = (const float*)d_in[0];
    const float* ew    = (const float*)d_in[1];
    const float* W1    = (const float*)d_in[2];
    const float* b1    = (const float*)d_in[3];
    const float* gamma = (const float*)d_in[4];
    const float* beta  = (const float*)d_in[5];
    const int*   src   = (const int*)d_in[6];
    const int*   dst   = (const int*)d_in[7];
    float* out = (float*)d_out;

    k_zero<<<196, 256>>>();
    k_hist<<<(EE+255)/256, 256>>>(ew, dst);
    k_scan<<<1, 1024>>>();
    k_fill<<<(EE+255)/256, 256>>>(ew, src, dst);
    k_nodestats<<<1024, 256>>>(node);
    k_agg<<<(NN+7)/8, 256>>>(node);
    k_finalize<<<1, 256>>>(W1, b1, gamma, beta);
    k_gemm<<<(ROWS+255)/256, 256>>>(node, out);
}

// round 4
// speedup vs baseline: 1.4476x; 1.1302x over previous
#include <cuda_runtime.h>
#include <cuda_bf16.h>
#include <cstdint>

#define TT 4
#define NN 50000
#define DH 64
#define EE 800000
#define ROWS (TT*NN)       // 200000
#define NBANK 64
#define BN_EPS 1e-5f
#define SCAN_BLOCKS 196    // ceil(50000/256)

// ---------------- device scratch (static, no allocs) ----------------
__device__ __align__(16) float d_avg[(size_t)ROWS*DH];   // 51.2 MB avg_neighbor
__device__ int   d_cnt[NN];
__device__ int   d_offs[NN+1];
__device__ int   d_cursor[NN];
__device__ float d_Z[NN];
__device__ int   d_bsum[SCAN_BLOCKS];
__device__ int   d_boff[SCAN_BLOCKS];
__device__ int   d_csr_src[EE];
__device__ float d_csr_w[EE];
// banks: [bank][stat][col], stats: 0 sumAll,1 sqAll,2 sumLast,3 sqLast,4 sumAvg,5 sqAvg
__device__ float d_banks[NBANK*6*64];
// W' packed directly in m16n8k8 tf32 B-fragment order
__device__ __align__(16) uint4 d_Wfrag[3072];
__device__ __align__(16) float d_bp[64];

// ---------------- kernels ----------------
__global__ void k_zero() {
    int i = blockIdx.x*256 + threadIdx.x;
    if (i < NN) { d_cnt[i] = 0; d_Z[i] = 0.f; }
    if (i < NBANK*6*64) d_banks[i] = 0.f;
}

__global__ void k_hist(const float* __restrict__ ew, const int* __restrict__ dst) {
    int e = blockIdx.x*256 + threadIdx.x;
    if (e < EE) {
        int d = dst[e];
        atomicAdd(&d_cnt[d], 1);
        atomicAdd(&d_Z[d], ew[e]);
    }
}

// ---- 3-phase scan ----
__global__ void k_scanA() {     // per-block sum of 256 counts
    int i = blockIdx.x*256 + threadIdx.x;
    int v = (i < NN) ? d_cnt[i] : 0;
    #pragma unroll
    for (int s = 16; s > 0; s >>= 1) v += __shfl_down_sync(0xffffffffu, v, s);
    __shared__ int ws[8];
    if ((threadIdx.x & 31) == 0) ws[threadIdx.x >> 5] = v;
    __syncthreads();
    if (threadIdx.x == 0) {
        int t = 0;
        #pragma unroll
        for (int w = 0; w < 8; w++) t += ws[w];
        d_bsum[blockIdx.x] = t;
    }
}

__global__ void k_scanB() {     // 1 block, 256 threads: exclusive scan of block sums
    int tid = threadIdx.x, lane = tid & 31, wid = tid >> 5;
    int v = (tid < SCAN_BLOCKS) ? d_bsum[tid] : 0;
    int incl = v;
    #pragma unroll
    for (int s = 1; s < 32; s <<= 1) {
        int t = __shfl_up_sync(0xffffffffu, incl, s);
        if (lane >= s) incl += t;
    }
    __shared__ int wsum[8], wpre[8];
    if (lane == 31) wsum[wid] = incl;
    __syncthreads();
    if (tid == 0) {
        int r = 0;
        #pragma unroll
        for (int w = 0; w < 8; w++) { wpre[w] = r; r += wsum[w]; }
    }
    __syncthreads();
    if (tid < SCAN_BLOCKS) d_boff[tid] = incl - v + wpre[wid];
}

__global__ void k_scanC() {     // per-block exclusive scan + global offset
    int i = blockIdx.x*256 + threadIdx.x;
    int tid = threadIdx.x, lane = tid & 31, wid = tid >> 5;
    int v = (i < NN) ? d_cnt[i] : 0;
    int incl = v;
    #pragma unroll
    for (int s = 1; s < 32; s <<= 1) {
        int t = __shfl_up_sync(0xffffffffu, incl, s);
        if (lane >= s) incl += t;
    }
    __shared__ int wsum[8], wpre[8];
    if (lane == 31) wsum[wid] = incl;
    __syncthreads();
    if (tid == 0) {
        int r = 0;
        #pragma unroll
        for (int w = 0; w < 8; w++) { wpre[w] = r; r += wsum[w]; }
    }
    __syncthreads();
    if (i < NN) {
        int excl = incl - v + wpre[wid] + d_boff[blockIdx.x];
        d_offs[i] = excl;
        d_cursor[i] = excl;
    }
    if (i == 0) d_offs[NN] = EE;
}

__global__ void k_fill(const float* __restrict__ ew, const int* __restrict__ src,
                       const int* __restrict__ dst) {
    int e = blockIdx.x*256 + threadIdx.x;
    if (e < EE) {
        int d = dst[e];
        int p = atomicAdd(&d_cursor[d], 1);
        d_csr_src[p] = src[e];
        d_csr_w[p]   = ew[e];
    }
}

// gather aggregation: warp per node, ALL 4 timesteps fused + ALL column stats fused.
// lane owns cols {2*lane, 2*lane+1} (float2).
__global__ void __launch_bounds__(256) k_agg(const float* __restrict__ x) {
    int n    = blockIdx.x*8 + (threadIdx.x >> 5);
    int lane = threadIdx.x & 31;
    __shared__ float sv[64], sq[64];            // avg stats
    __shared__ float sA[64], qA[64], sL[64], qL[64];  // x stats (all / last)
    if (threadIdx.x < 64) {
        sv[threadIdx.x] = 0.f; sq[threadIdx.x] = 0.f;
        sA[threadIdx.x] = 0.f; qA[threadIdx.x] = 0.f;
        sL[threadIdx.x] = 0.f; qL[threadIdx.x] = 0.f;
    }
    __syncthreads();
    if (n < NN) {
        const float2* x2 = (const float2*)x;

        // ---- own-node rows: column stats of node_data ----
        size_t nb = (size_t)n*32 + lane;
        float2 w0 = x2[nb];
        float2 w1 = x2[(size_t)NN*32 + nb];
        float2 w2 = x2[(size_t)2*NN*32 + nb];
        float2 w3 = x2[(size_t)3*NN*32 + nb];
        atomicAdd(&sA[2*lane],   w0.x+w1.x+w2.x+w3.x);
        atomicAdd(&sA[2*lane+1], w0.y+w1.y+w2.y+w3.y);
        atomicAdd(&qA[2*lane],   w0.x*w0.x+w1.x*w1.x+w2.x*w2.x+w3.x*w3.x);
        atomicAdd(&qA[2*lane+1], w0.y*w0.y+w1.y*w1.y+w2.y*w2.y+w3.y*w3.y);
        atomicAdd(&sL[2*lane],   w3.x);
        atomicAdd(&sL[2*lane+1], w3.y);
        atomicAdd(&qL[2*lane],   w3.x*w3.x);
        atomicAdd(&qL[2*lane+1], w3.y*w3.y);

        // ---- neighborhood gather ----
        int e0 = d_offs[n], e1 = d_offs[n+1];
        float2 a0 = make_float2(0.f,0.f), a1 = a0, a2 = a0, a3 = a0;
        for (int base = e0; base < e1; base += 32) {
            int m = e1 - base; if (m > 32) m = 32;
            int   s = 0; float w = 0.f;
            if (lane < m) { s = d_csr_src[base+lane]; w = d_csr_w[base+lane]; }
            for (int k = 0; k < m; k++) {
                int    sk = __shfl_sync(0xffffffffu, s, k);
                float  wk = __shfl_sync(0xffffffffu, w, k);
                size_t ad = (size_t)sk*32 + lane;
                float2 v0 = x2[ad];
                float2 v1 = x2[(size_t)NN*32 + ad];
                float2 v2 = x2[(size_t)2*NN*32 + ad];
                float2 v3 = x2[(size_t)3*NN*32 + ad];
                a0.x = fmaf(wk, v0.x, a0.x); a0.y = fmaf(wk, v0.y, a0.y);
                a1.x = fmaf(wk, v1.x, a1.x); a1.y = fmaf(wk, v1.y, a1.y);
                a2.x = fmaf(wk, v2.x, a2.x); a2.y = fmaf(wk, v2.y, a2.y);
                a3.x = fmaf(wk, v3.x, a3.x); a3.y = fmaf(wk, v3.y, a3.y);
            }
        }
        float z = d_Z[n];
        float inv = (z == 0.f) ? 1.f : 1.f/z;     // matches reference Z[Z==0]=1
        a0.x *= inv; a0.y *= inv; a1.x *= inv; a1.y *= inv;
        a2.x *= inv; a2.y *= inv; a3.x *= inv; a3.y *= inv;
        float2* av = (float2*)d_avg;
        av[nb]                         = a0;
        av[(size_t)NN*32 + nb]         = a1;
        av[(size_t)2*NN*32 + nb]       = a2;
        av[(size_t)3*NN*32 + nb]       = a3;
        atomicAdd(&sv[2*lane],   a0.x + a1.x + a2.x + a3.x);
        atomicAdd(&sv[2*lane+1], a0.y + a1.y + a2.y + a3.y);
        atomicAdd(&sq[2*lane],   a0.x*a0.x + a1.x*a1.x + a2.x*a2.x + a3.x*a3.x);
        atomicAdd(&sq[2*lane+1], a0.y*a0.y + a1.y*a1.y + a2.y*a2.y + a3.y*a3.y);
    }
    __syncthreads();
    if (threadIdx.x < 64) {
        float* b = d_banks + (blockIdx.x & (NBANK-1))*(6*64);
        atomicAdd(&b[0*64 + threadIdx.x], sA[threadIdx.x]);
        atomicAdd(&b[1*64 + threadIdx.x], qA[threadIdx.x]);
        atomicAdd(&b[2*64 + threadIdx.x], sL[threadIdx.x]);
        atomicAdd(&b[3*64 + threadIdx.x], qL[threadIdx.x]);
        atomicAdd(&b[4*64 + threadIdx.x], sv[threadIdx.x]);
        atomicAdd(&b[5*64 + threadIdx.x], sq[threadIdx.x]);
    }
}

__device__ __forceinline__ unsigned to_tf32(float v) {
    unsigned u;
    asm("cvt.rna.tf32.f32 %0, %1;" : "=r"(u) : "f"(v));
    return u;
}

// fold BN into GEMM: build tf32 fragment-packed W' and fp32 b'
__global__ void k_finalize(const float* __restrict__ W1, const float* __restrict__ b1,
                           const float* __restrict__ gamma, const float* __restrict__ beta) {
    __shared__ float stat[6*64];
    __shared__ float s[192];
    __shared__ float tt[192];
    int tid = threadIdx.x;
    for (int k = tid; k < 6*64; k += 256) {
        float acc = 0.f;
        for (int b = 0; b < NBANK; b++) acc += d_banks[b*(6*64) + k];
        stat[k] = acc;
    }
    __syncthreads();
    if (tid < 192) {
        float sum, sq;
        if (tid < 64)       { sum = stat[0*64+tid];            sq = stat[1*64+tid]; }
        else if (tid < 128) { int c = tid-64;
                              sum = stat[0*64+c]-stat[2*64+c]; sq = stat[1*64+c]-stat[3*64+c]; }
        else                { int c = tid-128;
                              sum = stat[4*64+c];              sq = stat[5*64+c]; }
        float mu  = sum / (float)ROWS;
        float var = sq  / (float)ROWS - mu*mu;
        float sj  = gamma[tid] * rsqrtf(var + BN_EPS);
        s[tid]  = sj;
        tt[tid] = beta[tid] - mu*sj;
    }
    __syncthreads();
    for (int i = tid; i < 3072; i += 256) {
        int lane = i & 31;
        int ntp  = (i >> 5) & 3;
        int ksc  = i >> 7;               // c*8 + ks
        int j0   = ksc*8 + (lane & 3);
        int n0   = ntp*16 + (lane >> 2);
        uint4 v;
        v.x = to_tf32(W1[n0*192 + j0]       * s[j0]);
        v.y = to_tf32(W1[n0*192 + j0 + 4]   * s[j0+4]);
        v.z = to_tf32(W1[(n0+8)*192 + j0]   * s[j0]);
        v.w = to_tf32(W1[(n0+8)*192 + j0+4] * s[j0+4]);
        d_Wfrag[i] = v;
    }
    if (tid < 64) {
        float acc = b1[tid];
        for (int j = 0; j < 192; j++) acc += tt[j] * W1[tid*192 + j];
        d_bp[tid] = acc;
    }
}

__device__ __forceinline__ void mma8(float (&c)[4], const unsigned* a, unsigned b0, unsigned b1) {
    asm volatile("mma.sync.aligned.m16n8k8.row.col.f32.tf32.tf32.f32 "
        "{%0,%1,%2,%3}, {%4,%5,%6,%7}, {%8,%9}, {%0,%1,%2,%3};"
        : "+f"(c[0]), "+f"(c[1]), "+f"(c[2]), "+f"(c[3])
        : "r"(a[0]), "r"(a[1]), "r"(a[2]), "r"(a[3]), "r"(b0), "r"(b1));
}

// tensor-core GEMM+ReLU. Block = 8 warps, each warp 32 rows x 64 cols.
__global__ void __launch_bounds__(256) k_gemm(const float* __restrict__ x,
                                              float* __restrict__ out) {
    __shared__ uint4 wfrag[3072];   // 48KB, all 3 chunks of W'
    for (int i = threadIdx.x; i < 3072; i += 256) wfrag[i] = d_Wfrag[i];
    __syncthreads();

    int lane = threadIdx.x & 31, warp = threadIdx.x >> 5;
    int gid = lane >> 2, tig = lane & 3;
    int rbase = blockIdx.x*256 + warp*32 + gid;

    float acc[2][8][4];
    #pragma unroll
    for (int mt = 0; mt < 2; mt++)
        #pragma unroll
        for (int nt = 0; nt < 8; nt++)
            #pragma unroll
            for (int q = 0; q < 4; q++) acc[mt][nt][q] = 0.f;

    int rows[4];
    #pragma unroll
    for (int i = 0; i < 4; i++) rows[i] = rbase + i*8;

    #pragma unroll
    for (int c = 0; c < 3; c++) {
        const float* base = (c == 2) ? d_avg : x;
        int shift = (c == 1) ? NN : 0;
        const float* rp[4];
        bool vld[4];
        #pragma unroll
        for (int i = 0; i < 4; i++) {
            int re = rows[i] - shift;
            vld[i] = (re >= 0) && (rows[i] < ROWS);
            rp[i]  = base + (size_t)(vld[i] ? re : 0)*64;
        }
        #pragma unroll
        for (int ks = 0; ks < 8; ks++) {
            int col = ks*8 + tig;
            unsigned a[2][4];
            #pragma unroll
            for (int mt = 0; mt < 2; mt++) {
                a[mt][0] = to_tf32(vld[2*mt]   ? rp[2*mt][col]     : 0.f);
                a[mt][1] = to_tf32(vld[2*mt+1] ? rp[2*mt+1][col]   : 0.f);
                a[mt][2] = to_tf32(vld[2*mt]   ? rp[2*mt][col+4]   : 0.f);
                a[mt][3] = to_tf32(vld[2*mt+1] ? rp[2*mt+1][col+4] : 0.f);
            }
            const uint4* wb = &wfrag[((c*8 + ks)*4)*32 + lane];
            #pragma unroll
            for (int ntp = 0; ntp < 4; ntp++) {
                uint4 b = wb[ntp*32];
                mma8(acc[0][2*ntp],   a[0], b.x, b.y);
                mma8(acc[1][2*ntp],   a[1], b.x, b.y);
                mma8(acc[0][2*ntp+1], a[0], b.z, b.w);
                mma8(acc[1][2*ntp+1], a[1], b.z, b.w);
            }
        }
    }

    float2* out2 = (float2*)out;
    const float2* bp2 = (const float2*)d_bp;
    #pragma unroll
    for (int mt = 0; mt < 2; mt++) {
        int r0 = rbase + mt*16;
        int r1 = r0 + 8;
        #pragma unroll
        for (int nt = 0; nt < 8; nt++) {
            float2 bb = bp2[nt*4 + tig];
            if (r0 < ROWS) {
                float2 o;
                o.x = fmaxf(acc[mt][nt][0] + bb.x, 0.f);
                o.y = fmaxf(acc[mt][nt][1] + bb.y, 0.f);
                out2[(size_t)r0*32 + nt*4 + tig] = o;
            }
            if (r1 < ROWS) {
                float2 o;
                o.x = fmaxf(acc[mt][nt][2] + bb.x, 0.f);
                o.y = fmaxf(acc[mt][nt][3] + bb.y, 0.f);
                out2[(size_t)r1*32 + nt*4 + tig] = o;
            }
        }
    }
}

// ---------------- launch ----------------
extern "C" void kernel_launch(void* const* d_in, const int* in_sizes, int n_in,
                              void* d_out, int out_size) {
    const float* node  = (const float*)d_in[0];
    const float* ew    = (const float*)d_in[1];
    const float* W1    = (const float*)d_in[2];
    const float* b1    = (const float*)d_in[3];
    const float* gamma = (const float*)d_in[4];
    const float* beta  = (const float*)d_in[5];
    const int*   src   = (const int*)d_in[6];
    const int*   dst   = (const int*)d_in[7];
    float* out = (float*)d_out;

    k_zero<<<SCAN_BLOCKS, 256>>>();
    k_hist<<<(EE+255)/256, 256>>>(ew, dst);
    k_scanA<<<SCAN_BLOCKS, 256>>>();
    k_scanB<<<1, 256>>>();
    k_scanC<<<SCAN_BLOCKS, 256>>>();
    k_fill<<<(EE+255)/256, 256>>>(ew, src, dst);
    k_agg<<<(NN+7)/8, 256>>>(node);
    k_finalize<<<1, 256>>>(W1, b1, gamma, beta);
    k_gemm<<<(ROWS+255)/256, 256>>>(node, out);
}